// round 5
// baseline (speedup 1.0000x reference)
#include <cuda_runtime.h>
#include <cuda_fp16.h>
#include <cuda_bf16.h>

#define NMAX 100000
#define EMAX 1600000
#define SCAN_CHUNK 1024

// ---------------------------------------------------------------------------
// Scratch (device globals — zero-init at load; each consumer restores zeros
// so the invariant holds across CUDA-graph replays).
// ---------------------------------------------------------------------------
__device__ int    g_deg[NMAX];
__device__ int    g_off[NMAX];        // CSR range begin (by dst)
__device__ int    g_end[NMAX];        // CSR range end
__device__ int    g_cur[NMAX];        // fill cursors
__device__ int    g_csrc[EMAX];       // CSR column = src node per edge
__device__ int    g_base;             // global edge-slot counter
__device__ float  g_dinv[NMAX];
__device__ float  g_xs[NMAX * 4];     // x * dinv (pre-scaled layer-1 sources)
__device__ float  g_a1[NMAX * 4];     // layer-1 aggregate (REDs from k_fill)
__device__ __half g_h2h[NMAX * 32];   // (relu(v@W1+b1) @ W2) * dinv, fp16

// ---------------------------------------------------------------------------
// red.global.add.v4.f32 (sm_90+): fire-and-forget vector atomic add
// ---------------------------------------------------------------------------
__device__ __forceinline__ void red_add_v4(float* p, float4 v) {
    asm volatile(
        "{\n\t"
        ".reg .u64 q;\n\t"
        "cvta.to.global.u64 q, %0;\n\t"
        "red.global.add.v4.f32 [q], {%1, %2, %3, %4};\n\t"
        "}"
        :: "l"(p), "f"(v.x), "f"(v.y), "f"(v.z), "f"(v.w)
        : "memory");
}

// ---------------------------------------------------------------------------
// K1: degree over dst (int4 vectorized); also resets g_base
// ---------------------------------------------------------------------------
__global__ void k_deg(const int* __restrict__ dst, int E) {
    int i = blockIdx.x * blockDim.x + threadIdx.x;
    if (i == 0) g_base = 0;
    int e = i * 4;
    if (e + 4 <= E) {
        int4 d = *(const int4*)&dst[e];
        atomicAdd(&g_deg[d.x], 1);
        atomicAdd(&g_deg[d.y], 1);
        atomicAdd(&g_deg[d.z], 1);
        atomicAdd(&g_deg[d.w], 1);
    } else {
        for (; e < E; e++) atomicAdd(&g_deg[dst[e]], 1);
    }
}

// ---------------------------------------------------------------------------
// K2: single-pass chunked scan, atomic base per 1024-chunk (ranges disjoint,
//     not globally sorted — g_end stores explicit ends). Also computes dinv,
//     pre-scales x, and ZEROES g_deg.
// ---------------------------------------------------------------------------
__global__ void __launch_bounds__(SCAN_CHUNK) k_scan(const float4* __restrict__ x4, int n) {
    __shared__ int swarp[32];
    __shared__ int sbase;
    int t = threadIdx.x;
    int lane = t & 31, wid = t >> 5;
    int i = blockIdx.x * SCAN_CHUNK + t;
    int v = (i < n) ? g_deg[i] : 0;

    int inc = v;
#pragma unroll
    for (int o = 1; o < 32; o <<= 1) {
        int y = __shfl_up_sync(0xffffffff, inc, o);
        if (lane >= o) inc += y;
    }
    if (lane == 31) swarp[wid] = inc;
    __syncthreads();
    if (t < 32) {
        int wv = swarp[t];
        int winc = wv;
#pragma unroll
        for (int o = 1; o < 32; o <<= 1) {
            int y = __shfl_up_sync(0xffffffff, winc, o);
            if (t >= o) winc += y;
        }
        swarp[t] = winc - wv;                          // exclusive warp base
        if (t == 31) sbase = atomicAdd(&g_base, winc); // winc = block total
    }
    __syncthreads();

    if (i < n) {
        int beg = sbase + swarp[wid] + (inc - v);
        g_off[i] = beg;
        g_cur[i] = beg;
        g_end[i] = beg + v;
        float di = rsqrtf((float)(v + 1));             // +1 self-loop
        g_dinv[i] = di;
        float4 xv = x4[i];
        xv.x *= di; xv.y *= di; xv.z *= di; xv.w *= di;
        *(float4*)&g_xs[i * 4] = xv;
        g_deg[i] = 0;                                  // restore scratch
    }
}

// ---------------------------------------------------------------------------
// K3: bucket-fill CSR + fused layer-1 scatter, 4 edges per thread:
//     csrc[pos] = src[e];  a1[dst] += xs[src]   (red.v4, 16B/edge)
// ---------------------------------------------------------------------------
__global__ void k_fill(const int* __restrict__ src,
                       const int* __restrict__ dst, int E) {
    int i = blockIdx.x * blockDim.x + threadIdx.x;
    int e = i * 4;
    if (e + 4 <= E) {
        int4 s4 = *(const int4*)&src[e];
        int4 d4 = *(const int4*)&dst[e];
        int ss[4] = {s4.x, s4.y, s4.z, s4.w};
        int dd[4] = {d4.x, d4.y, d4.z, d4.w};
#pragma unroll
        for (int k = 0; k < 4; k++) {
            int pos = atomicAdd(&g_cur[dd[k]], 1);
            g_csrc[pos] = ss[k];
            red_add_v4(&g_a1[dd[k] * 4], *(const float4*)&g_xs[ss[k] * 4]);
        }
    } else {
        for (; e < E; e++) {
            int s = src[e], d = dst[e];
            int pos = atomicAdd(&g_cur[d], 1);
            g_csrc[pos] = s;
            red_add_v4(&g_a1[d * 4], *(const float4*)&g_xs[s * 4]);
        }
    }
}

// ---------------------------------------------------------------------------
// K4: layer-1 transform, TWO threads per node (q = 0/1, 16 outputs each):
//     v = dinv*(a1 + xs);  h1 = relu(v@W1+b1);  h2h = fp16((h1@W2)*dinv)
//     W1 transposed into shared as float4 columns. Zeroes g_a1 after use.
// ---------------------------------------------------------------------------
__global__ void __launch_bounds__(256) k_layer1(
        const float* __restrict__ W1,   // [4,64]
        const float* __restrict__ b1,   // [64]
        const float* __restrict__ W2,   // [64,32]
        int n) {
    __shared__ float4 sW1t[64];         // column f of W1
    __shared__ float  sb1[64];
    __shared__ float  sW2[64 * 32];
    int t = threadIdx.x;
    if (t < 64) {
        sW1t[t] = make_float4(W1[t], W1[64 + t], W1[128 + t], W1[192 + t]);
        sb1[t] = b1[t];
    }
    for (int i = t; i < 2048; i += 256) sW2[i] = W2[i];
    __syncthreads();

    int node = blockIdx.x * 128 + (t >> 1);
    int q = t & 1;                       // which 16-output half
    if (node >= n) return;

    float di = g_dinv[node];
    float4 a  = *(const float4*)&g_a1[node * 4];
    float4 xv = *(const float4*)&g_xs[node * 4];
    if (q == 0)                          // restore zeros (one thread per node)
        *(float4*)&g_a1[node * 4] = make_float4(0.f, 0.f, 0.f, 0.f);
    float v0 = (a.x + xv.x) * di;
    float v1 = (a.y + xv.y) * di;
    float v2 = (a.z + xv.z) * di;
    float v3 = (a.w + xv.w) * di;

    float acc[16];
#pragma unroll
    for (int j = 0; j < 16; j++) acc[j] = 0.0f;

    const float4* w2base = (const float4*)&sW2[q * 16];

#pragma unroll 4
    for (int f = 0; f < 64; f++) {
        float4 w1 = sW1t[f];
        float h = fmaf(v0, w1.x, fmaf(v1, w1.y,
                  fmaf(v2, w1.z, fmaf(v3, w1.w, sb1[f]))));
        h = fmaxf(h, 0.0f);
        // 16 consecutive W2 values for this half: sW2[f*32 + q*16 .. +16)
        const float4* w2 = (const float4*)((const float*)w2base + f * 32);
#pragma unroll
        for (int c = 0; c < 4; c++) {
            float4 w = w2[c];
            acc[4 * c + 0] = fmaf(h, w.x, acc[4 * c + 0]);
            acc[4 * c + 1] = fmaf(h, w.y, acc[4 * c + 1]);
            acc[4 * c + 2] = fmaf(h, w.z, acc[4 * c + 2]);
            acc[4 * c + 3] = fmaf(h, w.w, acc[4 * c + 3]);
        }
    }

    // pack 16 fp32 -> 8 half2 -> two 16B stores
    __half2 hp[8];
#pragma unroll
    for (int c = 0; c < 8; c++)
        hp[c] = __floats2half2_rn(acc[2 * c] * di, acc[2 * c + 1] * di);
    float4* o = (float4*)&g_h2h[node * 32 + q * 16];
    o[0] = *(const float4*)&hp[0];
    o[1] = *(const float4*)&hp[4];
}

// ---------------------------------------------------------------------------
// K5: fused layer 2 + final linear (warp per node, lane = feature):
//     h2  = relu(dinv*(sum_s h2h[s] + h2h[node]) + b2)
//     out = relu(h2 @ Wf + bf)
//     CSR gather: each edge = one coalesced 64B (fp16) line, no atomics.
// ---------------------------------------------------------------------------
__global__ void __launch_bounds__(256) k_final(
        const float* __restrict__ b2,   // [32]
        const float* __restrict__ Wf,   // [32,32]
        const float* __restrict__ bf,   // [32]
        float* __restrict__ out, int n) {
    __shared__ float sWf[32 * 32];
    __shared__ float sb2[32];
    __shared__ float sbf[32];
    __shared__ float sh[8][32];
    int t = threadIdx.x;
    for (int i = t; i < 1024; i += 256) sWf[i] = Wf[i];
    if (t < 32) { sb2[t] = b2[t]; sbf[t] = bf[t]; }
    __syncthreads();

    int w = t >> 5, j = t & 31;
    int node = blockIdx.x * 8 + w;
    if (node >= n) return;

    int beg = g_off[node], end = g_end[node];
    float acc = 0.0f;
    int i = beg;
    for (; i + 8 <= end; i += 8) {
        int s0 = g_csrc[i + 0], s1 = g_csrc[i + 1];
        int s2 = g_csrc[i + 2], s3 = g_csrc[i + 3];
        int s4 = g_csrc[i + 4], s5 = g_csrc[i + 5];
        int s6 = g_csrc[i + 6], s7 = g_csrc[i + 7];
        float m0 = __half2float(g_h2h[s0 * 32 + j]);
        float m1 = __half2float(g_h2h[s1 * 32 + j]);
        float m2 = __half2float(g_h2h[s2 * 32 + j]);
        float m3 = __half2float(g_h2h[s3 * 32 + j]);
        float m4 = __half2float(g_h2h[s4 * 32 + j]);
        float m5 = __half2float(g_h2h[s5 * 32 + j]);
        float m6 = __half2float(g_h2h[s6 * 32 + j]);
        float m7 = __half2float(g_h2h[s7 * 32 + j]);
        acc += ((m0 + m1) + (m2 + m3)) + ((m4 + m5) + (m6 + m7));
    }
    for (; i < end; i++)
        acc += __half2float(g_h2h[g_csrc[i] * 32 + j]);

    float di = g_dinv[node];
    float self = __half2float(g_h2h[node * 32 + j]);
    float h = fmaxf(fmaf(di, acc + self, sb2[j]), 0.0f);
    sh[w][j] = h;
    __syncwarp();

    float o = sbf[j];
#pragma unroll
    for (int k = 0; k < 32; k++)
        o = fmaf(sh[w][k], sWf[k * 32 + j], o);
    out[node * 32 + j] = fmaxf(o, 0.0f);
}

// ---------------------------------------------------------------------------
// Launch — 5 kernels
// Inputs: x[N,4], edge_index[2,E], W1[4,64], b1[64], W2[64,32], b2[32],
//         Wf[32,32], bf[32]       Output: [N,32] float32
// ---------------------------------------------------------------------------
extern "C" void kernel_launch(void* const* d_in, const int* in_sizes, int n_in,
                              void* d_out, int out_size) {
    const float* x  = (const float*)d_in[0];
    const int*   ei = (const int*)d_in[1];
    const float* W1 = (const float*)d_in[2];
    const float* b1 = (const float*)d_in[3];
    const float* W2 = (const float*)d_in[4];
    const float* b2 = (const float*)d_in[5];
    const float* Wf = (const float*)d_in[6];
    const float* bf = (const float*)d_in[7];
    float* out = (float*)d_out;

    int n = in_sizes[0] / 4;
    int E = in_sizes[1] / 2;
    const int* src = ei;
    const int* dst = ei + E;

    const int T = 256;
    int nb = (n + SCAN_CHUNK - 1) / SCAN_CHUNK;

    k_deg<<<((E + 3) / 4 + T - 1) / T, T>>>(dst, E);
    k_scan<<<nb, SCAN_CHUNK>>>((const float4*)x, n);
    k_fill<<<((E + 3) / 4 + T - 1) / T, T>>>(src, dst, E);
    k_layer1<<<(n + 127) / 128, T>>>(W1, b1, W2, n);
    k_final<<<(n + 7) / 8, T>>>(b2, Wf, bf, out, n);
}

// round 6
// speedup vs baseline: 1.0463x; 1.0463x over previous
#include <cuda_runtime.h>
#include <cuda_fp16.h>
#include <cuda_bf16.h>

#define NMAX 100000
#define EMAX 1600000
#define SCAN_CHUNK 1024

// ---------------------------------------------------------------------------
// Scratch (device globals — zero-init at load; each consumer restores zeros
// so the invariant holds across CUDA-graph replays).
// ---------------------------------------------------------------------------
__device__ int    g_deg[NMAX];
__device__ int    g_off[NMAX];        // CSR range begin (by dst)
__device__ int    g_end[NMAX];        // CSR range end
__device__ int    g_rank[EMAX];       // edge rank within its dst bucket
__device__ int    g_csrc[EMAX];       // CSR column = src node per edge
__device__ int    g_base;             // global edge-slot counter
__device__ float  g_dinv[NMAX];
__device__ float  g_xs[NMAX * 4];     // x * dinv (pre-scaled layer-1 sources)
__device__ float  g_a1[NMAX * 4];     // layer-1 aggregate (REDs from k_fill)
__device__ __half g_h2h[NMAX * 32];   // (relu(v@W1+b1) @ W2) * dinv, fp16

// ---------------------------------------------------------------------------
// PTX helpers
// ---------------------------------------------------------------------------
__device__ __forceinline__ void red_add_v4(float* p, float4 v) {
    asm volatile(
        "{\n\t"
        ".reg .u64 q;\n\t"
        "cvta.to.global.u64 q, %0;\n\t"
        "red.global.add.v4.f32 [q], {%1, %2, %3, %4};\n\t"
        "}"
        :: "l"(p), "f"(v.x), "f"(v.y), "f"(v.z), "f"(v.w)
        : "memory");
}

// packed fp32x2 FMA (Blackwell FFMA2): d = a*b + d, two lanes at once
__device__ __forceinline__ void ffma2(unsigned long long& d,
                                      unsigned long long a,
                                      unsigned long long b) {
    asm("fma.rn.f32x2 %0, %1, %2, %0;" : "+l"(d) : "l"(a), "l"(b));
}

__device__ __forceinline__ void lds_v2u64(unsigned long long& a,
                                          unsigned long long& b,
                                          unsigned int addr) {
    asm volatile("ld.shared.v2.u64 {%0, %1}, [%2];"
                 : "=l"(a), "=l"(b) : "r"(addr));
}

// ---------------------------------------------------------------------------
// K1: degree over dst; rank[e] = arrival index within bucket; resets g_base
// ---------------------------------------------------------------------------
__global__ void k_deg(const int* __restrict__ dst, int E) {
    int e = blockIdx.x * blockDim.x + threadIdx.x;
    if (e == 0) g_base = 0;
    if (e < E) g_rank[e] = atomicAdd(&g_deg[dst[e]], 1);
}

// ---------------------------------------------------------------------------
// K2: single-pass chunked scan, atomic base per 1024-chunk (bucket ranges
//     disjoint, not globally sorted — g_end stores explicit ends). Also
//     computes dinv, pre-scales x, and ZEROES g_deg.
// ---------------------------------------------------------------------------
__global__ void __launch_bounds__(SCAN_CHUNK) k_scan(const float4* __restrict__ x4, int n) {
    __shared__ int swarp[32];
    __shared__ int sbase;
    int t = threadIdx.x;
    int lane = t & 31, wid = t >> 5;
    int i = blockIdx.x * SCAN_CHUNK + t;
    int v = (i < n) ? g_deg[i] : 0;

    int inc = v;
#pragma unroll
    for (int o = 1; o < 32; o <<= 1) {
        int y = __shfl_up_sync(0xffffffff, inc, o);
        if (lane >= o) inc += y;
    }
    if (lane == 31) swarp[wid] = inc;
    __syncthreads();
    if (t < 32) {
        int wv = swarp[t];
        int winc = wv;
#pragma unroll
        for (int o = 1; o < 32; o <<= 1) {
            int y = __shfl_up_sync(0xffffffff, winc, o);
            if (t >= o) winc += y;
        }
        swarp[t] = winc - wv;                          // exclusive warp base
        if (t == 31) sbase = atomicAdd(&g_base, winc); // winc = block total
    }
    __syncthreads();

    if (i < n) {
        int beg = sbase + swarp[wid] + (inc - v);
        g_off[i] = beg;
        g_end[i] = beg + v;
        float di = rsqrtf((float)(v + 1));             // +1 self-loop
        g_dinv[i] = di;
        float4 xv = x4[i];
        xv.x *= di; xv.y *= di; xv.z *= di; xv.w *= di;
        *(float4*)&g_xs[i * 4] = xv;
        g_deg[i] = 0;                                  // restore scratch
    }
}

// ---------------------------------------------------------------------------
// K3: bucket-fill CSR (atomic-free via precomputed rank) + layer-1 scatter:
//     csrc[off[d]+rank[e]] = src[e];  a1[dst] += xs[src]   (red.v4)
// ---------------------------------------------------------------------------
__global__ void k_fill(const int* __restrict__ src,
                       const int* __restrict__ dst, int E) {
    int e = blockIdx.x * blockDim.x + threadIdx.x;
    if (e >= E) return;
    int s = src[e], d = dst[e];
    g_csrc[g_off[d] + g_rank[e]] = s;
    red_add_v4(&g_a1[d * 4], *(const float4*)&g_xs[s * 4]);
}

// ---------------------------------------------------------------------------
// K4: layer-1 transform, TWO threads per node (q = 0/1, 16 outputs each):
//     v = dinv*(a1 + xs);  h1 = relu(v@W1+b1);  h2h = fp16((h1@W2)*dinv)
//     Inner product uses packed f32x2 FFMA2 (8 instr instead of 16).
// ---------------------------------------------------------------------------
__global__ void __launch_bounds__(256) k_layer1(
        const float* __restrict__ W1,   // [4,64]
        const float* __restrict__ b1,   // [64]
        const float* __restrict__ W2,   // [64,32]
        int n) {
    __shared__ float4 sW1t[64];         // column f of W1
    __shared__ float  sb1[64];
    __shared__ float  sW2[64 * 32];
    int t = threadIdx.x;
    if (t < 64) {
        sW1t[t] = make_float4(W1[t], W1[64 + t], W1[128 + t], W1[192 + t]);
        sb1[t] = b1[t];
    }
    for (int i = t; i < 2048; i += 256) sW2[i] = W2[i];
    __syncthreads();

    unsigned int sw2base = (unsigned int)__cvta_generic_to_shared(sW2);

    int node = blockIdx.x * 128 + (t >> 1);
    int q = t & 1;                       // which 16-output half
    if (node >= n) return;

    float di = g_dinv[node];
    float4 a  = *(const float4*)&g_a1[node * 4];
    float4 xv = *(const float4*)&g_xs[node * 4];
    if (q == 0)                          // restore zeros (one thread per node)
        *(float4*)&g_a1[node * 4] = make_float4(0.f, 0.f, 0.f, 0.f);
    float v0 = (a.x + xv.x) * di;
    float v1 = (a.y + xv.y) * di;
    float v2 = (a.z + xv.z) * di;
    float v3 = (a.w + xv.w) * di;

    unsigned long long acc[8];
#pragma unroll
    for (int c = 0; c < 8; c++) acc[c] = 0ull;

#pragma unroll 4
    for (int f = 0; f < 64; f++) {
        float4 w1 = sW1t[f];
        float h = fmaf(v0, w1.x, fmaf(v1, w1.y,
                  fmaf(v2, w1.z, fmaf(v3, w1.w, sb1[f]))));
        h = fmaxf(h, 0.0f);
        unsigned long long hh;
        asm("mov.b64 %0, {%1, %1};" : "=l"(hh) : "f"(h));

        unsigned int aaddr = sw2base + (unsigned)(f * 128 + q * 64);
        unsigned long long p0, p1, p2, p3, p4, p5, p6, p7;
        lds_v2u64(p0, p1, aaddr);
        lds_v2u64(p2, p3, aaddr + 16);
        lds_v2u64(p4, p5, aaddr + 32);
        lds_v2u64(p6, p7, aaddr + 48);
        ffma2(acc[0], p0, hh);
        ffma2(acc[1], p1, hh);
        ffma2(acc[2], p2, hh);
        ffma2(acc[3], p3, hh);
        ffma2(acc[4], p4, hh);
        ffma2(acc[5], p5, hh);
        ffma2(acc[6], p6, hh);
        ffma2(acc[7], p7, hh);
    }

    // unpack 8 f32x2 -> 16 fp32, scale by dinv, pack to fp16
    __half2 hp[8];
#pragma unroll
    for (int c = 0; c < 8; c++) {
        float lo, hi;
        asm("mov.b64 {%0, %1}, %2;" : "=f"(lo), "=f"(hi) : "l"(acc[c]));
        hp[c] = __floats2half2_rn(lo * di, hi * di);
    }
    float4* o = (float4*)&g_h2h[node * 32 + q * 16];
    o[0] = *(const float4*)&hp[0];
    o[1] = *(const float4*)&hp[4];
}

// ---------------------------------------------------------------------------
// K5: fused layer 2 + final linear (warp per node, lane = feature):
//     h2  = relu(dinv*(sum_s h2h[s] + h2h[node]) + b2)
//     out = relu(h2 @ Wf + bf)
//     CSR gather: each edge = one coalesced 64B fp16 line, no atomics.
// ---------------------------------------------------------------------------
__global__ void __launch_bounds__(256) k_final(
        const float* __restrict__ b2,   // [32]
        const float* __restrict__ Wf,   // [32,32]
        const float* __restrict__ bf,   // [32]
        float* __restrict__ out, int n) {
    __shared__ float sWf[32 * 32];
    __shared__ float sb2[32];
    __shared__ float sbf[32];
    __shared__ float sh[8][32];
    int t = threadIdx.x;
    for (int i = t; i < 1024; i += 256) sWf[i] = Wf[i];
    if (t < 32) { sb2[t] = b2[t]; sbf[t] = bf[t]; }
    __syncthreads();

    int w = t >> 5, j = t & 31;
    int node = blockIdx.x * 8 + w;
    if (node >= n) return;

    int beg = g_off[node], end = g_end[node];
    float acc = 0.0f;
    int i = beg;
    for (; i + 8 <= end; i += 8) {
        int s0 = g_csrc[i + 0], s1 = g_csrc[i + 1];
        int s2 = g_csrc[i + 2], s3 = g_csrc[i + 3];
        int s4 = g_csrc[i + 4], s5 = g_csrc[i + 5];
        int s6 = g_csrc[i + 6], s7 = g_csrc[i + 7];
        float m0 = __half2float(g_h2h[s0 * 32 + j]);
        float m1 = __half2float(g_h2h[s1 * 32 + j]);
        float m2 = __half2float(g_h2h[s2 * 32 + j]);
        float m3 = __half2float(g_h2h[s3 * 32 + j]);
        float m4 = __half2float(g_h2h[s4 * 32 + j]);
        float m5 = __half2float(g_h2h[s5 * 32 + j]);
        float m6 = __half2float(g_h2h[s6 * 32 + j]);
        float m7 = __half2float(g_h2h[s7 * 32 + j]);
        acc += ((m0 + m1) + (m2 + m3)) + ((m4 + m5) + (m6 + m7));
    }
    for (; i < end; i++)
        acc += __half2float(g_h2h[g_csrc[i] * 32 + j]);

    float di = g_dinv[node];
    float self = __half2float(g_h2h[node * 32 + j]);
    float h = fmaxf(fmaf(di, acc + self, sb2[j]), 0.0f);
    sh[w][j] = h;
    __syncwarp();

    float o = sbf[j];
#pragma unroll
    for (int k = 0; k < 32; k++)
        o = fmaf(sh[w][k], sWf[k * 32 + j], o);
    out[node * 32 + j] = fmaxf(o, 0.0f);
}

// ---------------------------------------------------------------------------
// Launch — 5 kernels
// Inputs: x[N,4], edge_index[2,E], W1[4,64], b1[64], W2[64,32], b2[32],
//         Wf[32,32], bf[32]       Output: [N,32] float32
// ---------------------------------------------------------------------------
extern "C" void kernel_launch(void* const* d_in, const int* in_sizes, int n_in,
                              void* d_out, int out_size) {
    const float* x  = (const float*)d_in[0];
    const int*   ei = (const int*)d_in[1];
    const float* W1 = (const float*)d_in[2];
    const float* b1 = (const float*)d_in[3];
    const float* W2 = (const float*)d_in[4];
    const float* b2 = (const float*)d_in[5];
    const float* Wf = (const float*)d_in[6];
    const float* bf = (const float*)d_in[7];
    float* out = (float*)d_out;

    int n = in_sizes[0] / 4;
    int E = in_sizes[1] / 2;
    const int* src = ei;
    const int* dst = ei + E;

    const int T = 256;
    int nb = (n + SCAN_CHUNK - 1) / SCAN_CHUNK;

    k_deg<<<(E + T - 1) / T, T>>>(dst, E);
    k_scan<<<nb, SCAN_CHUNK>>>((const float4*)x, n);
    k_fill<<<(E + T - 1) / T, T>>>(src, dst, E);
    k_layer1<<<(n + 127) / 128, T>>>(W1, b1, W2, n);
    k_final<<<(n + 7) / 8, T>>>(b2, Wf, bf, out, n);
}

// round 7
// speedup vs baseline: 1.0865x; 1.0385x over previous
#include <cuda_runtime.h>
#include <cuda_fp16.h>
#include <cuda_bf16.h>

#define NMAX 100000
#define EMAX 1600000
#define SCAN_CHUNK 1024

// ---------------------------------------------------------------------------
// Scratch (device globals — zero-init at load; each consumer restores zeros
// so the invariant holds across CUDA-graph replays).
// ---------------------------------------------------------------------------
__device__ int    g_deg[NMAX];
__device__ int    g_off[NMAX];        // CSR range begin (by dst)
__device__ int    g_end[NMAX];        // CSR range end
__device__ int    g_rank[EMAX];       // edge rank within its dst bucket
__device__ int    g_csrc[EMAX];       // CSR column = src node per edge
__device__ int    g_base;             // global edge-slot counter
__device__ float  g_dinv[NMAX];
__device__ float  g_xs[NMAX * 4];     // x * dinv (pre-scaled layer-1 sources)
__device__ float  g_a1[NMAX * 4];     // layer-1 aggregate (REDs from k_fill)
__device__ __half g_h2h[NMAX * 32];   // (relu(v@W1+b1) @ W2) * dinv, fp16

// ---------------------------------------------------------------------------
// PTX helpers
// ---------------------------------------------------------------------------
__device__ __forceinline__ void red_add_v4(float* p, float4 v) {
    asm volatile(
        "{\n\t"
        ".reg .u64 q;\n\t"
        "cvta.to.global.u64 q, %0;\n\t"
        "red.global.add.v4.f32 [q], {%1, %2, %3, %4};\n\t"
        "}"
        :: "l"(p), "f"(v.x), "f"(v.y), "f"(v.z), "f"(v.w)
        : "memory");
}

// packed fp32x2 FMA (Blackwell FFMA2): d = a*b + d
__device__ __forceinline__ void ffma2(unsigned long long& d,
                                      unsigned long long a,
                                      unsigned long long b) {
    asm("fma.rn.f32x2 %0, %1, %2, %0;" : "+l"(d) : "l"(a), "l"(b));
}

__device__ __forceinline__ unsigned long long pack2(float lo, float hi) {
    unsigned long long r;
    asm("mov.b64 %0, {%1, %2};" : "=l"(r) : "f"(lo), "f"(hi));
    return r;
}

__device__ __forceinline__ void unpack2(float& lo, float& hi,
                                        unsigned long long v) {
    asm("mov.b64 {%0, %1}, %2;" : "=f"(lo), "=f"(hi) : "l"(v));
}

// ---------------------------------------------------------------------------
// K1: degree over dst; rank[e] = arrival index within bucket; resets g_base
// ---------------------------------------------------------------------------
__global__ void k_deg(const int* __restrict__ dst, int E) {
    int e = blockIdx.x * blockDim.x + threadIdx.x;
    if (e == 0) g_base = 0;
    if (e < E) g_rank[e] = atomicAdd(&g_deg[dst[e]], 1);
}

// ---------------------------------------------------------------------------
// K2: single-pass chunked scan, atomic base per 1024-chunk (bucket ranges
//     disjoint, not globally sorted — g_end stores explicit ends). Also
//     computes dinv, pre-scales x, and ZEROES g_deg.
// ---------------------------------------------------------------------------
__global__ void __launch_bounds__(SCAN_CHUNK) k_scan(const float4* __restrict__ x4, int n) {
    __shared__ int swarp[32];
    __shared__ int sbase;
    int t = threadIdx.x;
    int lane = t & 31, wid = t >> 5;
    int i = blockIdx.x * SCAN_CHUNK + t;
    int v = (i < n) ? g_deg[i] : 0;

    int inc = v;
#pragma unroll
    for (int o = 1; o < 32; o <<= 1) {
        int y = __shfl_up_sync(0xffffffff, inc, o);
        if (lane >= o) inc += y;
    }
    if (lane == 31) swarp[wid] = inc;
    __syncthreads();
    if (t < 32) {
        int wv = swarp[t];
        int winc = wv;
#pragma unroll
        for (int o = 1; o < 32; o <<= 1) {
            int y = __shfl_up_sync(0xffffffff, winc, o);
            if (t >= o) winc += y;
        }
        swarp[t] = winc - wv;                          // exclusive warp base
        if (t == 31) sbase = atomicAdd(&g_base, winc); // winc = block total
    }
    __syncthreads();

    if (i < n) {
        int beg = sbase + swarp[wid] + (inc - v);
        g_off[i] = beg;
        g_end[i] = beg + v;
        float di = rsqrtf((float)(v + 1));             // +1 self-loop
        g_dinv[i] = di;
        float4 xv = x4[i];
        xv.x *= di; xv.y *= di; xv.z *= di; xv.w *= di;
        *(float4*)&g_xs[i * 4] = xv;
        g_deg[i] = 0;                                  // restore scratch
    }
}

// ---------------------------------------------------------------------------
// K3: bucket-fill CSR (atomic-free via precomputed rank) + layer-1 scatter:
//     csrc[off[d]+rank[e]] = src[e];  a1[dst] += xs[src]   (red.v4)
// ---------------------------------------------------------------------------
__global__ void k_fill(const int* __restrict__ src,
                       const int* __restrict__ dst, int E) {
    int e = blockIdx.x * blockDim.x + threadIdx.x;
    if (e >= E) return;
    int s = src[e], d = dst[e];
    g_csrc[g_off[d] + g_rank[e]] = s;
    red_add_v4(&g_a1[d * 4], *(const float4*)&g_xs[s * 4]);
}

// ---------------------------------------------------------------------------
// K4: layer-1 transform. Each thread: TWO nodes (A=i, B=i+128) x one
//     16-output half (q). W2 loads amortize over both nodes; h1 computed
//     exactly once per node. v = dinv*(a1+xs); h1 = relu(v@W1+b1);
//     h2h = fp16((h1@W2)*dinv). Zeroes g_a1 after use.
// ---------------------------------------------------------------------------
__global__ void __launch_bounds__(256) k_layer1(
        const float* __restrict__ W1,   // [4,64]
        const float* __restrict__ b1,   // [64]
        const float* __restrict__ W2,   // [64,32]
        int n) {
    __shared__ float4 sW1t[64];                 // column f of W1
    __shared__ float  sb1[64];
    __shared__ unsigned long long sW2p[64 * 16];// row f as 16 f32x2 pairs
    int t = threadIdx.x;
    if (t < 64) {
        sW1t[t] = make_float4(W1[t], W1[64 + t], W1[128 + t], W1[192 + t]);
        sb1[t] = b1[t];
    }
    for (int i = t; i < 1024; i += 256)
        sW2p[i] = ((const unsigned long long*)W2)[i];
    __syncthreads();

    int q = t & 1;                    // output half: features [q*16, q*16+16)
    int iA = blockIdx.x * 256 + (t >> 1);
    int iB = iA + 128;
    if (iA >= n) return;
    bool hasB = (iB < n);

    // --- node A inputs ---
    float diA = g_dinv[iA];
    float4 aA  = *(const float4*)&g_a1[iA * 4];
    float4 xA  = *(const float4*)&g_xs[iA * 4];
    if (q == 0) *(float4*)&g_a1[iA * 4] = make_float4(0.f, 0.f, 0.f, 0.f);
    float vA0 = (aA.x + xA.x) * diA, vA1 = (aA.y + xA.y) * diA;
    float vA2 = (aA.z + xA.z) * diA, vA3 = (aA.w + xA.w) * diA;

    // --- node B inputs (guarded) ---
    float diB = 0.f, vB0 = 0.f, vB1 = 0.f, vB2 = 0.f, vB3 = 0.f;
    if (hasB) {
        diB = g_dinv[iB];
        float4 aB = *(const float4*)&g_a1[iB * 4];
        float4 xB = *(const float4*)&g_xs[iB * 4];
        if (q == 0) *(float4*)&g_a1[iB * 4] = make_float4(0.f, 0.f, 0.f, 0.f);
        vB0 = (aB.x + xB.x) * diB; vB1 = (aB.y + xB.y) * diB;
        vB2 = (aB.z + xB.z) * diB; vB3 = (aB.w + xB.w) * diB;
    }

    unsigned long long accA[8], accB[8];
#pragma unroll
    for (int c = 0; c < 8; c++) { accA[c] = 0ull; accB[c] = 0ull; }

    const ulonglong2* w2p = (const ulonglong2*)&sW2p[q * 8];

#pragma unroll 4
    for (int f = 0; f < 64; f++) {
        float4 w1 = sW1t[f];
        float bb = sb1[f];
        float hA = fmaf(vA0, w1.x, fmaf(vA1, w1.y,
                   fmaf(vA2, w1.z, fmaf(vA3, w1.w, bb))));
        hA = fmaxf(hA, 0.0f);
        float hB = fmaf(vB0, w1.x, fmaf(vB1, w1.y,
                   fmaf(vB2, w1.z, fmaf(vB3, w1.w, bb))));
        hB = fmaxf(hB, 0.0f);
        unsigned long long hhA = pack2(hA, hA);
        unsigned long long hhB = pack2(hB, hB);

        const ulonglong2* w2 = (const ulonglong2*)((const unsigned long long*)w2p + f * 16);
        ulonglong2 p0 = w2[0], p1 = w2[1], p2 = w2[2], p3 = w2[3];
        ffma2(accA[0], p0.x, hhA); ffma2(accB[0], p0.x, hhB);
        ffma2(accA[1], p0.y, hhA); ffma2(accB[1], p0.y, hhB);
        ffma2(accA[2], p1.x, hhA); ffma2(accB[2], p1.x, hhB);
        ffma2(accA[3], p1.y, hhA); ffma2(accB[3], p1.y, hhB);
        ffma2(accA[4], p2.x, hhA); ffma2(accB[4], p2.x, hhB);
        ffma2(accA[5], p2.y, hhA); ffma2(accB[5], p2.y, hhB);
        ffma2(accA[6], p3.x, hhA); ffma2(accB[6], p3.x, hhB);
        ffma2(accA[7], p3.y, hhA); ffma2(accB[7], p3.y, hhB);
    }

    // epilogue: unpack, scale by dinv, pack fp16, store 16B per node-half
    {
        __half2 hp[4];
#pragma unroll
        for (int c = 0; c < 4; c++) {
            float lo, hi;
            unpack2(lo, hi, accA[c]);
            hp[c] = __floats2half2_rn(lo * diA, hi * diA);
        }
        ((float4*)&g_h2h[iA * 32 + q * 16])[0] = *(const float4*)hp;
#pragma unroll
        for (int c = 0; c < 4; c++) {
            float lo, hi;
            unpack2(lo, hi, accA[c + 4]);
            hp[c] = __floats2half2_rn(lo * diA, hi * diA);
        }
        ((float4*)&g_h2h[iA * 32 + q * 16])[1] = *(const float4*)hp;
    }
    if (hasB) {
        __half2 hp[4];
#pragma unroll
        for (int c = 0; c < 4; c++) {
            float lo, hi;
            unpack2(lo, hi, accB[c]);
            hp[c] = __floats2half2_rn(lo * diB, hi * diB);
        }
        ((float4*)&g_h2h[iB * 32 + q * 16])[0] = *(const float4*)hp;
#pragma unroll
        for (int c = 0; c < 4; c++) {
            float lo, hi;
            unpack2(lo, hi, accB[c + 4]);
            hp[c] = __floats2half2_rn(lo * diB, hi * diB);
        }
        ((float4*)&g_h2h[iB * 32 + q * 16])[1] = *(const float4*)hp;
    }
}

// ---------------------------------------------------------------------------
// K5: fused layer 2 + final linear (warp per node, lane = feature):
//     h2  = relu(dinv*(sum_s h2h[s] + h2h[node]) + b2)
//     out = relu(h2 @ Wf + bf)
//     CSR gather: each edge = one coalesced 64B fp16 line, no atomics.
// ---------------------------------------------------------------------------
__global__ void __launch_bounds__(256) k_final(
        const float* __restrict__ b2,   // [32]
        const float* __restrict__ Wf,   // [32,32]
        const float* __restrict__ bf,   // [32]
        float* __restrict__ out, int n) {
    __shared__ float sWf[32 * 32];
    __shared__ float sb2[32];
    __shared__ float sbf[32];
    __shared__ float sh[8][32];
    int t = threadIdx.x;
    for (int i = t; i < 1024; i += 256) sWf[i] = Wf[i];
    if (t < 32) { sb2[t] = b2[t]; sbf[t] = bf[t]; }
    __syncthreads();

    int w = t >> 5, j = t & 31;
    int node = blockIdx.x * 8 + w;
    if (node >= n) return;

    int beg = g_off[node], end = g_end[node];
    float acc = 0.0f;
    int i = beg;
    for (; i + 8 <= end; i += 8) {
        int s0 = g_csrc[i + 0], s1 = g_csrc[i + 1];
        int s2 = g_csrc[i + 2], s3 = g_csrc[i + 3];
        int s4 = g_csrc[i + 4], s5 = g_csrc[i + 5];
        int s6 = g_csrc[i + 6], s7 = g_csrc[i + 7];
        float m0 = __half2float(g_h2h[s0 * 32 + j]);
        float m1 = __half2float(g_h2h[s1 * 32 + j]);
        float m2 = __half2float(g_h2h[s2 * 32 + j]);
        float m3 = __half2float(g_h2h[s3 * 32 + j]);
        float m4 = __half2float(g_h2h[s4 * 32 + j]);
        float m5 = __half2float(g_h2h[s5 * 32 + j]);
        float m6 = __half2float(g_h2h[s6 * 32 + j]);
        float m7 = __half2float(g_h2h[s7 * 32 + j]);
        acc += ((m0 + m1) + (m2 + m3)) + ((m4 + m5) + (m6 + m7));
    }
    for (; i < end; i++)
        acc += __half2float(g_h2h[g_csrc[i] * 32 + j]);

    float di = g_dinv[node];
    float self = __half2float(g_h2h[node * 32 + j]);
    float h = fmaxf(fmaf(di, acc + self, sb2[j]), 0.0f);
    sh[w][j] = h;
    __syncwarp();

    float o = sbf[j];
#pragma unroll
    for (int k = 0; k < 32; k++)
        o = fmaf(sh[w][k], sWf[k * 32 + j], o);
    out[node * 32 + j] = fmaxf(o, 0.0f);
}

// ---------------------------------------------------------------------------
// Launch — 5 kernels
// Inputs: x[N,4], edge_index[2,E], W1[4,64], b1[64], W2[64,32], b2[32],
//         Wf[32,32], bf[32]       Output: [N,32] float32
// ---------------------------------------------------------------------------
extern "C" void kernel_launch(void* const* d_in, const int* in_sizes, int n_in,
                              void* d_out, int out_size) {
    const float* x  = (const float*)d_in[0];
    const int*   ei = (const int*)d_in[1];
    const float* W1 = (const float*)d_in[2];
    const float* b1 = (const float*)d_in[3];
    const float* W2 = (const float*)d_in[4];
    const float* b2 = (const float*)d_in[5];
    const float* Wf = (const float*)d_in[6];
    const float* bf = (const float*)d_in[7];
    float* out = (float*)d_out;

    int n = in_sizes[0] / 4;
    int E = in_sizes[1] / 2;
    const int* src = ei;
    const int* dst = ei + E;

    const int T = 256;
    int nb = (n + SCAN_CHUNK - 1) / SCAN_CHUNK;

    k_deg<<<(E + T - 1) / T, T>>>(dst, E);
    k_scan<<<nb, SCAN_CHUNK>>>((const float4*)x, n);
    k_fill<<<(E + T - 1) / T, T>>>(src, dst, E);
    k_layer1<<<(n + 255) / 256, T>>>(W1, b1, W2, n);
    k_final<<<(n + 7) / 8, T>>>(b2, Wf, bf, out, n);
}

// round 9
// speedup vs baseline: 1.2301x; 1.1321x over previous
#include <cuda_runtime.h>
#include <cuda_fp16.h>
#include <cuda_bf16.h>

#define NMAX 100000
#define EMAX 1600000
#define SCAN_CHUNK 1024

// ---------------------------------------------------------------------------
// Scratch (device globals — zero-init at load; each consumer restores zeros
// so the invariant holds across CUDA-graph replays).
// ---------------------------------------------------------------------------
__device__ int    g_deg[NMAX];
__device__ int    g_off[NMAX];        // CSR range begin (by dst)
__device__ int    g_end[NMAX];        // CSR range end
__device__ int    g_rank[EMAX];       // edge rank within its dst bucket
__device__ int    g_csrc[EMAX];       // CSR column = src node BYTE offset (s*64)
__device__ int    g_base;             // global edge-slot counter
__device__ float  g_dinv[NMAX];
__device__ float  g_xs[NMAX * 4];     // x * dinv (pre-scaled layer-1 sources)
__device__ float  g_a1[NMAX * 4];     // layer-1 aggregate (REDs from k_fill)
__device__ __half g_h2h[NMAX * 32];   // (relu(v@W1+b1) @ W2) * dinv, fp16

// ---------------------------------------------------------------------------
// PTX helpers
// ---------------------------------------------------------------------------
__device__ __forceinline__ void red_add_v4(float* p, float4 v) {
    asm volatile(
        "{\n\t"
        ".reg .u64 q;\n\t"
        "cvta.to.global.u64 q, %0;\n\t"
        "red.global.add.v4.f32 [q], {%1, %2, %3, %4};\n\t"
        "}"
        :: "l"(p), "f"(v.x), "f"(v.y), "f"(v.z), "f"(v.w)
        : "memory");
}

// packed fp32x2 FMA (Blackwell FFMA2): d = a*b + d
__device__ __forceinline__ void ffma2(unsigned long long& d,
                                      unsigned long long a,
                                      unsigned long long b) {
    asm("fma.rn.f32x2 %0, %1, %2, %0;" : "+l"(d) : "l"(a), "l"(b));
}

__device__ __forceinline__ unsigned long long pack2(float lo, float hi) {
    unsigned long long r;
    asm("mov.b64 %0, {%1, %2};" : "=l"(r) : "f"(lo), "f"(hi));
    return r;
}

__device__ __forceinline__ void unpack2(float& lo, float& hi,
                                        unsigned long long v) {
    asm("mov.b64 {%0, %1}, %2;" : "=f"(lo), "=f"(hi) : "l"(v));
}

// ---------------------------------------------------------------------------
// K1: degree over dst; rank[e] = arrival index within bucket; resets g_base
// ---------------------------------------------------------------------------
__global__ void k_deg(const int* __restrict__ dst, int E) {
    int e = blockIdx.x * blockDim.x + threadIdx.x;
    if (e == 0) g_base = 0;
    if (e < E) g_rank[e] = atomicAdd(&g_deg[dst[e]], 1);
}

// ---------------------------------------------------------------------------
// K2: single-pass chunked scan, atomic base per 1024-chunk (bucket ranges
//     disjoint, not globally sorted — g_end stores explicit ends). Also
//     computes dinv, pre-scales x, and ZEROES g_deg.
// ---------------------------------------------------------------------------
__global__ void __launch_bounds__(SCAN_CHUNK) k_scan(const float4* __restrict__ x4, int n) {
    __shared__ int swarp[32];
    __shared__ int sbase;
    int t = threadIdx.x;
    int lane = t & 31, wid = t >> 5;
    int i = blockIdx.x * SCAN_CHUNK + t;
    int v = (i < n) ? g_deg[i] : 0;

    int inc = v;
#pragma unroll
    for (int o = 1; o < 32; o <<= 1) {
        int y = __shfl_up_sync(0xffffffff, inc, o);
        if (lane >= o) inc += y;
    }
    if (lane == 31) swarp[wid] = inc;
    __syncthreads();
    if (t < 32) {
        int wv = swarp[t];
        int winc = wv;
#pragma unroll
        for (int o = 1; o < 32; o <<= 1) {
            int y = __shfl_up_sync(0xffffffff, winc, o);
            if (t >= o) winc += y;
        }
        swarp[t] = winc - wv;                          // exclusive warp base
        if (t == 31) sbase = atomicAdd(&g_base, winc); // winc = block total
    }
    __syncthreads();

    if (i < n) {
        int beg = sbase + swarp[wid] + (inc - v);
        g_off[i] = beg;
        g_end[i] = beg + v;
        float di = rsqrtf((float)(v + 1));             // +1 self-loop
        g_dinv[i] = di;
        float4 xv = x4[i];
        xv.x *= di; xv.y *= di; xv.z *= di; xv.w *= di;
        *(float4*)&g_xs[i * 4] = xv;
        g_deg[i] = 0;                                  // restore scratch
    }
}

// ---------------------------------------------------------------------------
// K3: bucket-fill CSR (atomic-free via precomputed rank) + layer-1 scatter:
//     csrc[off[d]+rank[e]] = src[e]*64 (byte offset);  a1[dst] += xs[src]
// ---------------------------------------------------------------------------
__global__ void k_fill(const int* __restrict__ src,
                       const int* __restrict__ dst, int E) {
    int e = blockIdx.x * blockDim.x + threadIdx.x;
    if (e >= E) return;
    int s = src[e], d = dst[e];
    g_csrc[g_off[d] + g_rank[e]] = s << 6;   // byte offset into g_h2h row
    red_add_v4(&g_a1[d * 4], *(const float4*)&g_xs[s * 4]);
}

// ---------------------------------------------------------------------------
// K4: layer-1 transform. Each thread: TWO nodes (A=i, B=i+128) x one
//     16-output half (q). W2 loads amortize over both nodes; h1 computed
//     once per node per half. FFMA2 datapath. Zeroes g_a1 after use.
// ---------------------------------------------------------------------------
__global__ void __launch_bounds__(256) k_layer1(
        const float* __restrict__ W1,   // [4,64]
        const float* __restrict__ b1,   // [64]
        const float* __restrict__ W2,   // [64,32]
        int n) {
    __shared__ float4 sW1t[64];                 // column f of W1
    __shared__ float  sb1[64];
    __shared__ unsigned long long sW2p[64 * 16];// row f as 16 f32x2 pairs
    int t = threadIdx.x;
    if (t < 64) {
        sW1t[t] = make_float4(W1[t], W1[64 + t], W1[128 + t], W1[192 + t]);
        sb1[t] = b1[t];
    }
    for (int i = t; i < 1024; i += 256)
        sW2p[i] = ((const unsigned long long*)W2)[i];
    __syncthreads();

    int q = t & 1;                    // output half: features [q*16, q*16+16)
    int iA = blockIdx.x * 256 + (t >> 1);
    int iB = iA + 128;
    if (iA >= n) return;
    bool hasB = (iB < n);

    float diA = g_dinv[iA];
    float4 aA  = *(const float4*)&g_a1[iA * 4];
    float4 xA  = *(const float4*)&g_xs[iA * 4];
    if (q == 0) *(float4*)&g_a1[iA * 4] = make_float4(0.f, 0.f, 0.f, 0.f);
    float vA0 = (aA.x + xA.x) * diA, vA1 = (aA.y + xA.y) * diA;
    float vA2 = (aA.z + xA.z) * diA, vA3 = (aA.w + xA.w) * diA;

    float diB = 0.f, vB0 = 0.f, vB1 = 0.f, vB2 = 0.f, vB3 = 0.f;
    if (hasB) {
        diB = g_dinv[iB];
        float4 aB = *(const float4*)&g_a1[iB * 4];
        float4 xB = *(const float4*)&g_xs[iB * 4];
        if (q == 0) *(float4*)&g_a1[iB * 4] = make_float4(0.f, 0.f, 0.f, 0.f);
        vB0 = (aB.x + xB.x) * diB; vB1 = (aB.y + xB.y) * diB;
        vB2 = (aB.z + xB.z) * diB; vB3 = (aB.w + xB.w) * diB;
    }

    unsigned long long accA[8], accB[8];
#pragma unroll
    for (int c = 0; c < 8; c++) { accA[c] = 0ull; accB[c] = 0ull; }

    const ulonglong2* w2p = (const ulonglong2*)&sW2p[q * 8];

#pragma unroll 8
    for (int f = 0; f < 64; f++) {
        float4 w1 = sW1t[f];
        float bb = sb1[f];
        float hA = fmaf(vA0, w1.x, fmaf(vA1, w1.y,
                   fmaf(vA2, w1.z, fmaf(vA3, w1.w, bb))));
        hA = fmaxf(hA, 0.0f);
        float hB = fmaf(vB0, w1.x, fmaf(vB1, w1.y,
                   fmaf(vB2, w1.z, fmaf(vB3, w1.w, bb))));
        hB = fmaxf(hB, 0.0f);
        unsigned long long hhA = pack2(hA, hA);
        unsigned long long hhB = pack2(hB, hB);

        const ulonglong2* w2 = (const ulonglong2*)((const unsigned long long*)w2p + f * 16);
        ulonglong2 p0 = w2[0], p1 = w2[1], p2 = w2[2], p3 = w2[3];
        ffma2(accA[0], p0.x, hhA); ffma2(accB[0], p0.x, hhB);
        ffma2(accA[1], p0.y, hhA); ffma2(accB[1], p0.y, hhB);
        ffma2(accA[2], p1.x, hhA); ffma2(accB[2], p1.x, hhB);
        ffma2(accA[3], p1.y, hhA); ffma2(accB[3], p1.y, hhB);
        ffma2(accA[4], p2.x, hhA); ffma2(accB[4], p2.x, hhB);
        ffma2(accA[5], p2.y, hhA); ffma2(accB[5], p2.y, hhB);
        ffma2(accA[6], p3.x, hhA); ffma2(accB[6], p3.x, hhB);
        ffma2(accA[7], p3.y, hhA); ffma2(accB[7], p3.y, hhB);
    }

    {
        __half2 hp[4];
#pragma unroll
        for (int c = 0; c < 4; c++) {
            float lo, hi;
            unpack2(lo, hi, accA[c]);
            hp[c] = __floats2half2_rn(lo * diA, hi * diA);
        }
        ((float4*)&g_h2h[iA * 32 + q * 16])[0] = *(const float4*)hp;
#pragma unroll
        for (int c = 0; c < 4; c++) {
            float lo, hi;
            unpack2(lo, hi, accA[c + 4]);
            hp[c] = __floats2half2_rn(lo * diA, hi * diA);
        }
        ((float4*)&g_h2h[iA * 32 + q * 16])[1] = *(const float4*)hp;
    }
    if (hasB) {
        __half2 hp[4];
#pragma unroll
        for (int c = 0; c < 4; c++) {
            float lo, hi;
            unpack2(lo, hi, accB[c]);
            hp[c] = __floats2half2_rn(lo * diB, hi * diB);
        }
        ((float4*)&g_h2h[iB * 32 + q * 16])[0] = *(const float4*)hp;
#pragma unroll
        for (int c = 0; c < 4; c++) {
            float lo, hi;
            unpack2(lo, hi, accB[c + 4]);
            hp[c] = __floats2half2_rn(lo * diB, hi * diB);
        }
        ((float4*)&g_h2h[iB * 32 + q * 16])[1] = *(const float4*)hp;
    }
}

// ---------------------------------------------------------------------------
// K5: fused layer 2 + final linear. TWO nodes per warp:
//     lane = (half = lane>>4, j2 = lane&15) -> feature pair (2*j2, 2*j2+1)
//     Gather: one __half2 per lane per edge; a warp-instruction covers 2 edges.
//     h2  = relu(dinv*(sum_s h2h[s] + h2h[node]) + b2)
//     out = relu(h2 @ Wf + bf)
// ---------------------------------------------------------------------------
__global__ void __launch_bounds__(256) k_final(
        const float* __restrict__ b2,   // [32]
        const float* __restrict__ Wf,   // [32,32]
        const float* __restrict__ bf,   // [32]
        float* __restrict__ out, int n) {
    __shared__ float sWf[32 * 32];
    __shared__ float sb2[32];
    __shared__ float sbf[32];
    __shared__ float sh[16][32];        // 16 nodes per 256-thread block
    int t = threadIdx.x;
    for (int i = t; i < 1024; i += 256) sWf[i] = Wf[i];
    if (t < 32) { sb2[t] = b2[t]; sbf[t] = bf[t]; }
    __syncthreads();

    int w = t >> 5;
    int lane = t & 31;
    int half = lane >> 4;               // which node of the warp's pair
    int j2 = lane & 15;                 // feature pair index
    int slot = w * 2 + half;
    int node = blockIdx.x * 16 + slot;
    bool active = (node < n);

    const char* h2base = (const char*)g_h2h;
    int foff = j2 << 2;                 // byte offset of feature pair

    float ax = 0.0f, ay = 0.0f;
    float di = 0.0f;
    float2 selff = make_float2(0.f, 0.f);
    if (active) {
        int beg = g_off[node], end = g_end[node];
        int i = beg;
        for (; i + 4 <= end; i += 4) {
            int o0 = g_csrc[i + 0], o1 = g_csrc[i + 1];
            int o2 = g_csrc[i + 2], o3 = g_csrc[i + 3];
            __half2 m0 = *(const __half2*)(h2base + o0 + foff);
            __half2 m1 = *(const __half2*)(h2base + o1 + foff);
            __half2 m2 = *(const __half2*)(h2base + o2 + foff);
            __half2 m3 = *(const __half2*)(h2base + o3 + foff);
            float2 f0 = __half22float2(m0), f1 = __half22float2(m1);
            float2 f2 = __half22float2(m2), f3 = __half22float2(m3);
            ax += (f0.x + f1.x) + (f2.x + f3.x);
            ay += (f0.y + f1.y) + (f2.y + f3.y);
        }
        for (; i < end; i++) {
            __half2 m = *(const __half2*)(h2base + g_csrc[i] + foff);
            float2 f = __half22float2(m);
            ax += f.x; ay += f.y;
        }
        di = g_dinv[node];
        selff = __half22float2(*(const __half2*)(h2base + (node << 6) + foff));
    }

    float2 bb2 = *(const float2*)&sb2[j2 * 2];
    float h0 = fmaxf(fmaf(di, ax + selff.x, bb2.x), 0.0f);
    float h1 = fmaxf(fmaf(di, ay + selff.y, bb2.y), 0.0f);
    sh[slot][j2 * 2]     = h0;
    sh[slot][j2 * 2 + 1] = h1;
    __syncwarp();
    if (!active) return;

    float2 bbf = *(const float2*)&sbf[j2 * 2];
    float o0 = bbf.x, o1 = bbf.y;
#pragma unroll
    for (int k = 0; k < 32; k++) {
        float hk = sh[slot][k];
        float2 wv = *(const float2*)&sWf[k * 32 + j2 * 2];
        o0 = fmaf(hk, wv.x, o0);
        o1 = fmaf(hk, wv.y, o1);
    }
    // FINAL RELU (missing in R8 — the R8 correctness bug)
    *(float2*)&out[node * 32 + j2 * 2] =
        make_float2(fmaxf(o0, 0.0f), fmaxf(o1, 0.0f));
}

// ---------------------------------------------------------------------------
// Launch — 5 kernels
// Inputs: x[N,4], edge_index[2,E], W1[4,64], b1[64], W2[64,32], b2[32],
//         Wf[32,32], bf[32]       Output: [N,32] float32
// ---------------------------------------------------------------------------
extern "C" void kernel_launch(void* const* d_in, const int* in_sizes, int n_in,
                              void* d_out, int out_size) {
    const float* x  = (const float*)d_in[0];
    const int*   ei = (const int*)d_in[1];
    const float* W1 = (const float*)d_in[2];
    const float* b1 = (const float*)d_in[3];
    const float* W2 = (const float*)d_in[4];
    const float* b2 = (const float*)d_in[5];
    const float* Wf = (const float*)d_in[6];
    const float* bf = (const float*)d_in[7];
    float* out = (float*)d_out;

    int n = in_sizes[0] / 4;
    int E = in_sizes[1] / 2;
    const int* src = ei;
    const int* dst = ei + E;

    const int T = 256;
    int nb = (n + SCAN_CHUNK - 1) / SCAN_CHUNK;

    k_deg<<<(E + T - 1) / T, T>>>(dst, E);
    k_scan<<<nb, SCAN_CHUNK>>>((const float4*)x, n);
    k_fill<<<(E + T - 1) / T, T>>>(src, dst, E);
    k_layer1<<<(n + 255) / 256, T>>>(W1, b1, W2, n);
    k_final<<<(n + 15) / 16, T>>>(b2, Wf, bf, out, n);
}